// round 14
// baseline (speedup 1.0000x reference)
#include <cuda_runtime.h>
#include <cuda_fp16.h>
#include <cstdint>
#include <cstddef>

#define NB 1024
#define NT 64
#define NF 121
#define NH 512
#define NSEG 32
#define NG 2048   // 4*H

// ---------------- scratch (device globals; no allocation) ----------------
__device__ __align__(16) float   g_Z   [(size_t)NB * NT * NG];
__device__ __align__(16) __half  g_X   [(size_t)NB * NT * 128];
__device__ __align__(16) __half  g_Y   [(size_t)NB * NT * NH];
__device__ __align__(16) float   g_D1  [(size_t)NB * NSEG * NH];
__device__ __align__(16) __half  g_hA  [2][NB * NH];
__device__ __align__(16) __half  g_hB  [2][NB * NH];
__device__ __align__(16) float   g_cA  [NB * NH];
__device__ __align__(16) float   g_cB  [NB * NH];
#define O_eW0 0
#define O_eU0 (2048*128)
#define O_eW1 (O_eU0 + 2048*512)
#define O_eU1 (O_eW1 + 2048*512)
#define O_dU0 (O_eU1 + 2048*512)
#define O_dW1 (O_dU0 + 2048*512)
#define O_dU1 (O_dW1 + 2048*512)
#define W_TOTAL (O_dU1 + 2048*512)
__device__ __align__(16) __half  g_WT  [W_TOTAL];
__device__ __align__(16) float   g_bias[4 * NG];

// ---------------- helpers ----------------
__device__ __forceinline__ float rcpa(float x) {
    float r; asm("rcp.approx.f32 %0, %1;" : "=f"(r) : "f"(x)); return r;
}
__device__ __forceinline__ float sigf(float x)  { return rcpa(1.0f + __expf(-x)); }
__device__ __forceinline__ float tanhff(float x){ return __fmaf_rn(2.0f, rcpa(1.0f + __expf(-2.0f * x)), -1.0f); }

__device__ __forceinline__ uint32_t smem_u32(const void* p) {
    uint32_t a;
    asm("{ .reg .u64 t; cvta.to.shared.u64 t, %1; cvt.u32.u64 %0, t; }" : "=r"(a) : "l"(p));
    return a;
}
__device__ __forceinline__ void mma16816h(float* d, const unsigned* a, unsigned b0, unsigned b1) {
    asm volatile(
        "mma.sync.aligned.m16n8k16.row.col.f32.f16.f16.f32 "
        "{%0,%1,%2,%3}, {%4,%5,%6,%7}, {%8,%9}, {%0,%1,%2,%3};"
        : "+f"(d[0]), "+f"(d[1]), "+f"(d[2]), "+f"(d[3])
        : "r"(a[0]), "r"(a[1]), "r"(a[2]), "r"(a[3]), "r"(b0), "r"(b1));
}
__device__ __forceinline__ void ldsm4(uint32_t* r, uint32_t addr) {
    asm volatile("ldmatrix.sync.aligned.m8n8.x4.shared.b16 {%0,%1,%2,%3}, [%4];"
                 : "=r"(r[0]), "=r"(r[1]), "=r"(r[2]), "=r"(r[3]) : "r"(addr));
}
__device__ __forceinline__ void cpa16(uint32_t dst, const void* src) {
    asm volatile("cp.async.cg.shared.global [%0], [%1], 16;" :: "r"(dst), "l"(src));
}
#define CP_COMMIT() asm volatile("cp.async.commit_group;" ::: "memory")

// smem: two 20KB stages: A 4K | B 16K  (40KB total -> 4 CTAs/SM)
#define BUF_STRIDE 20480u
#define SMEM_DYN   (2 * 20480)

// ---------------- merged prep kernels ----------------
__global__ void k_prep_weights(const float* __restrict__ eW0, const float* __restrict__ eU0,
                               const float* __restrict__ eW1, const float* __restrict__ eU1,
                               const float* __restrict__ dU0, const float* __restrict__ dW1,
                               const float* __restrict__ dU1) {
    long long idx = (long long)blockIdx.x * blockDim.x + threadIdx.x;
    const float* src; int K, Kpad; size_t off;
    const long long S0 = 2048LL * 128, S = 2048LL * 512;
    if (idx < S0)               { src = eW0; K = NF;  Kpad = 128; off = O_eW0; }
    else if ((idx -= S0) < S)   { src = eU0; K = NH;  Kpad = 512; off = O_eU0; }
    else if ((idx -= S) < S)    { src = eW1; K = NH;  Kpad = 512; off = O_eW1; }
    else if ((idx -= S) < S)    { src = eU1; K = NH;  Kpad = 512; off = O_eU1; }
    else if ((idx -= S) < S)    { src = dU0; K = NH;  Kpad = 512; off = O_dU0; }
    else if ((idx -= S) < S)    { src = dW1; K = NH;  Kpad = 512; off = O_dW1; }
    else if ((idx -= S) < S)    { src = dU1; K = NH;  Kpad = 512; off = O_dU1; }
    else return;
    int n = (int)(idx / Kpad), k = (int)(idx % Kpad);
    float v = (k < K) ? src[(size_t)k * NG + n] : 0.0f;
    int cil = (n & 511) * 4 + (n >> 9);
    g_WT[off + (size_t)cil * Kpad + k] = __float2half(v);
}

__global__ void k_prep_misc(const float* __restrict__ x,
                            const float* __restrict__ eb0, const float* __restrict__ eb1,
                            const float* __restrict__ db0, const float* __restrict__ db1) {
    long long idx = (long long)blockIdx.x * blockDim.x + threadIdx.x;
    if (idx < 4 * NG) {
        int which = (int)(idx >> 11), n = (int)(idx & 2047);
        const float* b = (which == 0) ? eb0 : (which == 1) ? eb1 : (which == 2) ? db0 : db1;
        g_bias[which * NG + (n & 511) * 4 + (n >> 9)] = b[n];
        return;
    }
    idx -= 4 * NG;
    if (idx < (long long)NB * NT * 128) {
        int r = (int)(idx >> 7), k = (int)(idx & 127);
        g_X[idx] = __float2half((k < NF) ? x[(size_t)r * NF + k] : 0.0f);
        return;
    }
    idx -= (long long)NB * NT * 128;
    if (idx < NB * NH) {
        __half z = __float2half(0.0f);
        g_hA[0][idx] = z; g_hB[0][idx] = z;
        g_cA[idx] = 0.0f; g_cB[idx] = 0.0f;
    }
}

// ---------------- fp16 GEMM: 4 CTAs/SM, 2-stage, hoisted addressing, unrolled K ----------------
// Tile BM=32 x BN=128; 8 warps (2x4), warp tile 16x32. K chunks of 64 (NC chunks).
template <bool LSTM, int NC, bool PRE>
__global__ __launch_bounds__(256, 4)
void k_gemm1(const __half* __restrict__ A, int lda,
             const __half* __restrict__ B, int ldw,
             float* __restrict__ outZ,
             const float* __restrict__ pre, long long preStride,
             const float* __restrict__ bias,
             float* __restrict__ cState,
             __half* __restrict__ hOut,
             __half* __restrict__ yOut, long long yStride,
             float* __restrict__ yF32) {
    extern __shared__ __align__(128) char smem[];
    const uint32_t sb = smem_u32(smem);
    const int tid = threadIdx.x, lane = tid & 31, warp = tid >> 5;
    const int wm = warp >> 2;          // 0..1  (16 M-rows each)
    const int wn = warp & 3;           // 0..3  (32 N-cols each)
    const int bm = blockIdx.x * 32;
    const int bn = blockIdx.y * 128;

    float acc[4][4];
#pragma unroll
    for (int b = 0; b < 4; b++)
#pragma unroll
        for (int c = 0; c < 4; c++) acc[b][c] = 0.0f;

    // ---- hoisted LDSM offsets (per-thread constants) ----
    const uint32_t a_lc = (uint32_t)(lane & 16);
    const uint32_t b_lc = (uint32_t)((lane & 8) << 1);
    const int b_r8 = (lane & 16) >> 1;
    uint32_t aoff[4], boff[4][2];
    {
        const int ra = wm * 16 + (lane & 15);
        const uint32_t swa = (uint32_t)((ra & 7) * 16);
#pragma unroll
        for (int k16 = 0; k16 < 4; ++k16)
            aoff[k16] = (uint32_t)(ra * 128) + (((uint32_t)(k16 * 32) + a_lc) ^ swa);
#pragma unroll
        for (int jq = 0; jq < 2; ++jq) {
            const int rb = wn * 32 + jq * 16 + (lane & 7) + b_r8;
            const uint32_t swb = (uint32_t)((rb & 7) * 16);
#pragma unroll
            for (int k16 = 0; k16 < 4; ++k16)
                boff[k16][jq] = 4096u + (uint32_t)(rb * 128)
                              + (((uint32_t)(k16 * 32) + b_lc) ^ swb);
        }
    }

    // ---- hoisted cp.async pointers / smem offsets ----
    uint32_t sAoff, sBoff[4];
    const __half* pa;
    const __half* pb[4];
    {
        int row = tid >> 3, seg = tid & 7;
        sAoff = (uint32_t)(row * 128) + (uint32_t)((seg * 16) ^ ((row & 7) * 16));
        pa = A + (size_t)(bm + row) * lda + seg * 8;
#pragma unroll
        for (int it = 0; it < 4; it++) {
            int u = it * 256 + tid;
            int brow = u >> 3, bseg = u & 7;
            sBoff[it] = 4096u + (uint32_t)(brow * 128)
                      + (uint32_t)((bseg * 16) ^ ((brow & 7) * 16));
            pb[it] = B + (size_t)(bn + brow) * ldw + bseg * 8;
        }
    }

    auto issue = [&](uint32_t dbase) {
        cpa16(dbase + sAoff, pa); pa += 64;
#pragma unroll
        for (int it = 0; it < 4; it++) { cpa16(dbase + sBoff[it], pb[it]); pb[it] += 64; }
        CP_COMMIT();
    };

    issue(sb);
#pragma unroll
    for (int c = 0; c < NC; ++c) {
        asm volatile("cp.async.wait_group 0;" ::: "memory");
        __syncthreads();
        if (c + 1 < NC) issue(sb + (uint32_t)((c + 1) & 1) * BUF_STRIDE);
        const uint32_t dbase = sb + (uint32_t)(c & 1) * BUF_STRIDE;
#pragma unroll
        for (int k16 = 0; k16 < 4; ++k16) {
            uint32_t af[4];
            ldsm4(af, dbase + aoff[k16]);
            uint32_t bfr[4][2];
#pragma unroll
            for (int jq = 0; jq < 2; ++jq) {
                uint32_t t4[4];
                ldsm4(t4, dbase + boff[k16][jq]);
                bfr[jq * 2][0] = t4[0];     bfr[jq * 2][1] = t4[1];
                bfr[jq * 2 + 1][0] = t4[2]; bfr[jq * 2 + 1][1] = t4[3];
            }
#pragma unroll
            for (int jt = 0; jt < 4; ++jt)
                mma16816h(acc[jt], af, bfr[jt][0], bfr[jt][1]);
        }
    }

    // ---------------- epilogue ----------------
    if (!LSTM) {
        int r = bm + wm * 16 + (lane >> 2);
#pragma unroll
        for (int jt = 0; jt < 4; jt++) {
            int cix = bn + wn * 32 + jt * 8 + (lane & 3) * 2;
            float* o = outZ + (size_t)r * NG + cix;
            o[0] = acc[jt][0]; o[1] = acc[jt][1];
            o += (size_t)8 * NG;
            o[0] = acc[jt][2]; o[1] = acc[jt][3];
        }
    } else {
        const int par = lane & 1;
        const int rA = bm + wm * 16 + (lane >> 2);
        const int r  = rA + par * 8;
#pragma unroll
        for (int jt = 0; jt < 4; jt++) {
            const int cix = bn + wn * 32 + jt * 8 + (lane & 3) * 2;
            float z0 = acc[jt][0] + bias[cix];
            float z1 = acc[jt][1] + bias[cix + 1];
            float z2 = acc[jt][2] + bias[cix];
            float z3 = acc[jt][3] + bias[cix + 1];
            if (PRE) {
                z0 += pre[(size_t)rA * preStride + cix];
                z1 += pre[(size_t)rA * preStride + cix + 1];
                z2 += pre[(size_t)(rA + 8) * preStride + cix];
                z3 += pre[(size_t)(rA + 8) * preStride + cix + 1];
            }
            float s0 = par ? z0 : z2;
            float s1 = par ? z1 : z3;
            float q0 = __shfl_xor_sync(0xffffffffu, s0, 1);
            float q1 = __shfl_xor_sync(0xffffffffu, s1, 1);
            float zi = par ? q0 : z0;
            float zf = par ? q1 : z1;
            float zg = par ? z2 : q0;
            float zo = par ? z3 : q1;
            const int j = cix >> 2;
            const size_t si = (size_t)r * NH + j;
            float ig = sigf(zi), fg = sigf(zf), og = sigf(zo);
            float gg = tanhff(zg);
            float cn = fg * cState[si] + ig * gg;
            float h = og * tanhff(cn);
            cState[si] = cn;
            __half hh = __float2half(h);
            hOut[si] = hh;
            if (yOut) yOut[(size_t)r * yStride + j] = hh;
            if (yF32) yF32[(size_t)r * yStride + j] = h;
        }
    }
}

// ---------------- final dense ----------------
__global__ void k_dense(const float* __restrict__ w, const float* __restrict__ b,
                        float* __restrict__ out) {
    int r = blockIdx.x * 8 + (threadIdx.x >> 5);
    int lane = threadIdx.x & 31;
    const float* row = g_D1 + (size_t)r * NH;
    float s = 0.0f;
#pragma unroll
    for (int k = lane; k < NH; k += 32) s += row[k] * w[k];
#pragma unroll
    for (int o = 16; o; o >>= 1) s += __shfl_xor_sync(0xffffffffu, s, o);
    if (lane == 0) out[r] = s + b[0];
}

// ---------------- host ----------------
extern "C" void kernel_launch(void* const* d_in, const int* in_sizes, int n_in,
                              void* d_out, int out_size) {
    (void)in_sizes; (void)n_in; (void)out_size;
    const float* x      = (const float*)d_in[0];
    const float* eW0    = (const float*)d_in[2];
    const float* eU0    = (const float*)d_in[3];
    const float* eb0    = (const float*)d_in[4];
    const float* eW1    = (const float*)d_in[5];
    const float* eU1    = (const float*)d_in[6];
    const float* eb1    = (const float*)d_in[7];
    const float* dU0    = (const float*)d_in[9];
    const float* db0    = (const float*)d_in[10];
    const float* dW1    = (const float*)d_in[11];
    const float* dU1    = (const float*)d_in[12];
    const float* db1    = (const float*)d_in[13];
    const float* denseW = (const float*)d_in[14];
    const float* denseb = (const float*)d_in[15];

    cudaFuncSetAttribute(k_gemm1<true, 8, true>,   cudaFuncAttributeMaxDynamicSharedMemorySize, SMEM_DYN);
    cudaFuncSetAttribute(k_gemm1<true, 8, false>,  cudaFuncAttributeMaxDynamicSharedMemorySize, SMEM_DYN);
    cudaFuncSetAttribute(k_gemm1<false, 8, false>, cudaFuncAttributeMaxDynamicSharedMemorySize, SMEM_DYN);
    cudaFuncSetAttribute(k_gemm1<false, 2, false>, cudaFuncAttributeMaxDynamicSharedMemorySize, SMEM_DYN);

    void *pZ, *pX, *pY, *pD1, *pA, *pB, *pCA, *pCB, *pW, *pBs;
    cudaGetSymbolAddress(&pZ, g_Z);
    cudaGetSymbolAddress(&pX, g_X);
    cudaGetSymbolAddress(&pY, g_Y);
    cudaGetSymbolAddress(&pD1, g_D1);
    cudaGetSymbolAddress(&pA, g_hA);
    cudaGetSymbolAddress(&pB, g_hB);
    cudaGetSymbolAddress(&pCA, g_cA);  cudaGetSymbolAddress(&pCB, g_cB);
    cudaGetSymbolAddress(&pW, g_WT);
    cudaGetSymbolAddress(&pBs, g_bias);

    float* Z = (float*)pZ;
    __half* X = (__half*)pX;
    __half* Y = (__half*)pY;
    float* D1 = (float*)pD1;
    __half* hA[2] = {(__half*)pA, (__half*)pA + NB * NH};
    __half* hB[2] = {(__half*)pB, (__half*)pB + NB * NH};
    float* cA = (float*)pCA; float* cB = (float*)pCB;
    __half* W = (__half*)pW;
    float* Bias = (float*)pBs;

    // --- prep: 2 launches ---
    {
        long long wtot = 2048LL * 128 + 6LL * 2048 * 512;
        k_prep_weights<<<(int)((wtot + 255) / 256), 256>>>(eW0, eU0, eW1, eU1, dU0, dW1, dU1);
        long long mtot = 4LL * NG + (long long)NB * NT * 128 + (long long)NB * NH;
        k_prep_misc<<<(int)((mtot + 255) / 256), 256>>>(x, eb0, eb1, db0, db1);
    }

    const dim3 blk(256);
    const dim3 gStep(NB / 32, 16);   // 512 CTAs -> fully resident at 4 CTAs/SM

    // --- encoder L0: precompute x@eW0 (K=128), then 64 recurrent steps ---
    k_gemm1<false, 2, false><<<dim3(NB * NT / 32, 16), blk, SMEM_DYN>>>(
        X, 128, W + O_eW0, 128, Z,
        nullptr, 0, nullptr, nullptr, nullptr, nullptr, 0, nullptr);
    for (int t = 0; t < NT; t++) {
        k_gemm1<true, 8, true><<<gStep, blk, SMEM_DYN>>>(
            hA[t & 1], NH, W + O_eU0, NH, nullptr,
            Z + (size_t)t * NG, (long long)NT * NG, Bias + 0 * NG, cA,
            hA[(t + 1) & 1],
            Y + (size_t)t * NH, (long long)NT * NH, nullptr);
    }
    // --- encoder L1: precompute y0@eW1, then 64 steps ---
    k_gemm1<false, 8, false><<<dim3(NB * NT / 32, 16), blk, SMEM_DYN>>>(
        Y, NH, W + O_eW1, NH, Z,
        nullptr, 0, nullptr, nullptr, nullptr, nullptr, 0, nullptr);
    for (int t = 0; t < NT; t++) {
        k_gemm1<true, 8, true><<<gStep, blk, SMEM_DYN>>>(
            hB[t & 1], NH, W + O_eU1, NH, nullptr,
            Z + (size_t)t * NG, (long long)NT * NG, Bias + 1 * NG, cB,
            hB[(t + 1) & 1],
            nullptr, 0, nullptr);
    }
    // --- decoder L0: zero input; continues from enc-L0 final state ---
    for (int t = 0; t < NSEG; t++) {
        k_gemm1<true, 8, false><<<gStep, blk, SMEM_DYN>>>(
            hA[t & 1], NH, W + O_dU0, NH, nullptr,
            nullptr, 0, Bias + 2 * NG, cA,
            hA[(t + 1) & 1],
            Y + (size_t)t * NH, (long long)NSEG * NH, nullptr);
    }
    // --- decoder L1: precompute d0@dW1, then 32 steps, emit fp32 d1 ---
    k_gemm1<false, 8, false><<<dim3(NB * NSEG / 32, 16), blk, SMEM_DYN>>>(
        Y, NH, W + O_dW1, NH, Z,
        nullptr, 0, nullptr, nullptr, nullptr, nullptr, 0, nullptr);
    for (int t = 0; t < NSEG; t++) {
        k_gemm1<true, 8, true><<<gStep, blk, SMEM_DYN>>>(
            hB[t & 1], NH, W + O_dU1, NH, nullptr,
            Z + (size_t)t * NG, (long long)NSEG * NG, Bias + 3 * NG, cB,
            hB[(t + 1) & 1],
            nullptr, (long long)NSEG * NH, D1 + (size_t)t * NH);
    }
    // --- final dense ---
    k_dense<<<NB * NSEG / 8, 256>>>(denseW, denseb, (float*)d_out);
}

// round 15
// speedup vs baseline: 1.1484x; 1.1484x over previous
#include <cuda_runtime.h>
#include <cuda_fp16.h>
#include <cstdint>
#include <cstddef>

#define NB 1024
#define NT 64
#define NF 121
#define NH 512
#define NSEG 32
#define NG 2048   // 4*H

// ---------------- scratch (device globals; no allocation) ----------------
__device__ __align__(16) float   g_Z   [(size_t)NB * NT * NG];    // x@eW0 pre (interleaved cols)
__device__ __align__(16) __half  g_X   [(size_t)NB * NT * 128];
__device__ __align__(16) __half  g_Y   [(size_t)NB * NT * NH];    // y0 / d0 staging (fp16)
__device__ __align__(16) float   g_D1  [(size_t)NB * NSEG * NH];
__device__ __align__(16) __half  g_hA  [2][NB * NH];
__device__ __align__(16) __half  g_hB  [2][NB * NH];
__device__ __align__(16) float   g_cA  [NB * NH];
__device__ __align__(16) float   g_cB  [NB * NH];
// weight arena: W^T fp16, rows = interleaved out-col (j*4+gate), K contiguous.
// Sections: eW0 (Kpad 128), eU0 (512), eUW1 = [eU1|eW1] (1024), dU0 (512), dUW1 = [dU1|dW1] (1024)
#define O_eW0  0
#define O_eU0  (2048*128)
#define O_eUW1 (O_eU0 + 2048*512)
#define O_dU0  (O_eUW1 + 2048*1024)
#define O_dUW1 (O_dU0 + 2048*512)
#define W_TOTAL (O_dUW1 + 2048*1024)
__device__ __align__(16) __half  g_WT  [W_TOTAL];
__device__ __align__(16) float   g_bias[4 * NG];

// ---------------- helpers ----------------
__device__ __forceinline__ float rcpa(float x) {
    float r; asm("rcp.approx.f32 %0, %1;" : "=f"(r) : "f"(x)); return r;
}
__device__ __forceinline__ float sigf(float x)  { return rcpa(1.0f + __expf(-x)); }
__device__ __forceinline__ float tanhff(float x){ return __fmaf_rn(2.0f, rcpa(1.0f + __expf(-2.0f * x)), -1.0f); }

__device__ __forceinline__ uint32_t smem_u32(const void* p) {
    uint32_t a;
    asm("{ .reg .u64 t; cvta.to.shared.u64 t, %1; cvt.u32.u64 %0, t; }" : "=r"(a) : "l"(p));
    return a;
}
__device__ __forceinline__ void mma16816h(float* d, const unsigned* a, unsigned b0, unsigned b1) {
    asm volatile(
        "mma.sync.aligned.m16n8k16.row.col.f32.f16.f16.f32 "
        "{%0,%1,%2,%3}, {%4,%5,%6,%7}, {%8,%9}, {%0,%1,%2,%3};"
        : "+f"(d[0]), "+f"(d[1]), "+f"(d[2]), "+f"(d[3])
        : "r"(a[0]), "r"(a[1]), "r"(a[2]), "r"(a[3]), "r"(b0), "r"(b1));
}
__device__ __forceinline__ void ldsm4(uint32_t* r, uint32_t addr) {
    asm volatile("ldmatrix.sync.aligned.m8n8.x4.shared.b16 {%0,%1,%2,%3}, [%4];"
                 : "=r"(r[0]), "=r"(r[1]), "=r"(r[2]), "=r"(r[3]) : "r"(addr));
}
__device__ __forceinline__ void cpa16(uint32_t dst, const void* src) {
    asm volatile("cp.async.cg.shared.global [%0], [%1], 16;" :: "r"(dst), "l"(src));
}
#define CP_COMMIT() asm volatile("cp.async.commit_group;" ::: "memory")

// smem: two 20KB stages: A 4K | B 16K  (40KB total -> 4 CTAs/SM)
#define BUF_STRIDE 20480u
#define SMEM_DYN   (2 * 20480)

// ---------------- merged prep kernels ----------------
__global__ void k_prep_weights(const float* __restrict__ eW0, const float* __restrict__ eU0,
                               const float* __restrict__ eW1, const float* __restrict__ eU1,
                               const float* __restrict__ dU0, const float* __restrict__ dW1,
                               const float* __restrict__ dU1) {
    long long idx = (long long)blockIdx.x * blockDim.x + threadIdx.x;
    const long long S128 = 2048LL * 128, S512 = 2048LL * 512, S1024 = 2048LL * 1024;
    const float *s0 = nullptr, *s1 = nullptr;   // s1 = second K-half (concat)
    int Kpad, K0;
    size_t off;
    if (idx < S128)              { s0 = eW0; K0 = NF;  Kpad = 128;  off = O_eW0; }
    else if ((idx -= S128) < S512)  { s0 = eU0; K0 = NH; Kpad = 512;  off = O_eU0; }
    else if ((idx -= S512) < S1024) { s0 = eU1; s1 = eW1; K0 = NH; Kpad = 1024; off = O_eUW1; }
    else if ((idx -= S1024) < S512) { s0 = dU0; K0 = NH; Kpad = 512;  off = O_dU0; }
    else if ((idx -= S512) < S1024) { s0 = dU1; s1 = dW1; K0 = NH; Kpad = 1024; off = O_dUW1; }
    else return;
    int n = (int)(idx / Kpad), k = (int)(idx % Kpad);
    float v;
    if (k < K0)           v = s0[(size_t)k * NG + n];
    else if (s1)          v = s1[(size_t)(k - 512) * NG + n];
    else                  v = 0.0f;
    int cil = (n & 511) * 4 + (n >> 9);
    g_WT[off + (size_t)cil * Kpad + k] = __float2half(v);
}

__global__ void k_prep_misc(const float* __restrict__ x,
                            const float* __restrict__ eb0, const float* __restrict__ eb1,
                            const float* __restrict__ db0, const float* __restrict__ db1) {
    long long idx = (long long)blockIdx.x * blockDim.x + threadIdx.x;
    if (idx < 4 * NG) {
        int which = (int)(idx >> 11), n = (int)(idx & 2047);
        const float* b = (which == 0) ? eb0 : (which == 1) ? eb1 : (which == 2) ? db0 : db1;
        g_bias[which * NG + (n & 511) * 4 + (n >> 9)] = b[n];
        return;
    }
    idx -= 4 * NG;
    if (idx < (long long)NB * NT * 128) {
        int r = (int)(idx >> 7), k = (int)(idx & 127);
        g_X[idx] = __float2half((k < NF) ? x[(size_t)r * NF + k] : 0.0f);
        return;
    }
    idx -= (long long)NB * NT * 128;
    if (idx < NB * NH) {
        __half z = __float2half(0.0f);
        g_hA[0][idx] = z; g_hB[0][idx] = z;
        g_cA[idx] = 0.0f; g_cB[idx] = 0.0f;
    }
}

// ---------------- step params ----------------
struct StepP {
    const __half* A;  int lda;      // K-half 0 (h state)
    const __half* A2; int lda2;     // K-half 1 (layer input), nullptr if K=512
    const __half* B;  int ldw;      // weight rows, ldw = Kpad
    int nc;                         // K chunks of 64 (8 or 16)
    const float* pre; long long preStride;
    const float* bias;
    float* cState;
    __half* hOut;
    __half* yOut; long long yStride;
    float* yF32;
};

// ---------------- LSTM step GEMM: grid (32,16,z), z selects params ----------------
// Tile BM=32 x BN=128; 8 warps (2x4), warp tile 16x32. 2 smem stages, runtime nc.
__global__ __launch_bounds__(256, 4)
void k_step(StepP p0, StepP p1) {
    const StepP p = (blockIdx.z == 0) ? p0 : p1;
    extern __shared__ __align__(128) char smem[];
    const uint32_t sb = smem_u32(smem);
    const int tid = threadIdx.x, lane = tid & 31, warp = tid >> 5;
    const int wm = warp >> 2;
    const int wn = warp & 3;
    const int bm = blockIdx.x * 32;
    const int bn = blockIdx.y * 128;

    float acc[4][4];
#pragma unroll
    for (int b = 0; b < 4; b++)
#pragma unroll
        for (int c = 0; c < 4; c++) acc[b][c] = 0.0f;

    const uint32_t a_lc = (uint32_t)(lane & 16);
    const uint32_t b_lc = (uint32_t)((lane & 8) << 1);
    const int b_r8 = (lane & 16) >> 1;

    auto issue = [&](int c) {
        const uint32_t dbase = sb + (uint32_t)(c & 1) * BUF_STRIDE;
        {   // A: 32 rows x 128B; chunks >= 8 come from A2 (K-concat)
            int kb = c * 64;
            const __half* Ab = p.A; int ldA = p.lda;
            if (c >= 8) { Ab = p.A2; ldA = p.lda2; kb -= 512; }
            int row = tid >> 3, seg = tid & 7;
            uint32_t off = (uint32_t)(row * 128) + (uint32_t)((seg * 16) ^ ((row & 7) * 16));
            cpa16(dbase + off, Ab + (size_t)(bm + row) * ldA + kb + seg * 8);
        }
        {   // B: 128 rows x 128B
            const int kb = c * 64;
            const uint32_t db = dbase + 4096u;
#pragma unroll
            for (int it = 0; it < 4; it++) {
                int u = it * 256 + tid;
                int row = u >> 3, seg = u & 7;
                uint32_t off = (uint32_t)(row * 128) + (uint32_t)((seg * 16) ^ ((row & 7) * 16));
                cpa16(db + off, p.B + (size_t)(bn + row) * p.ldw + kb + seg * 8);
            }
        }
        CP_COMMIT();
    };

    const int nc = p.nc;
    issue(0);
    for (int c = 0; c < nc; ++c) {
        asm volatile("cp.async.wait_group 0;" ::: "memory");
        __syncthreads();
        if (c + 1 < nc) issue(c + 1);
        const uint32_t dbase = sb + (uint32_t)(c & 1) * BUF_STRIDE;
#pragma unroll
        for (int k16 = 0; k16 < 4; ++k16) {
            const uint32_t kcol = (uint32_t)(k16 * 32);
            uint32_t af[4];
            {
                int r = wm * 16 + (lane & 15);
                uint32_t addr = dbase + (uint32_t)(r * 128)
                              + ((kcol + a_lc) ^ (uint32_t)((r & 7) * 16));
                ldsm4(af, addr);
            }
            uint32_t bfr[4][2];
#pragma unroll
            for (int jq = 0; jq < 2; ++jq) {
                int r = wn * 32 + jq * 16 + (lane & 7) + b_r8;
                uint32_t addr = dbase + 4096u + (uint32_t)(r * 128)
                              + ((kcol + b_lc) ^ (uint32_t)((r & 7) * 16));
                uint32_t t4[4];
                ldsm4(t4, addr);
                bfr[jq * 2][0] = t4[0];     bfr[jq * 2][1] = t4[1];
                bfr[jq * 2 + 1][0] = t4[2]; bfr[jq * 2 + 1][1] = t4[3];
            }
#pragma unroll
            for (int jt = 0; jt < 4; ++jt)
                mma16816h(acc[jt], af, bfr[jt][0], bfr[jt][1]);
        }
    }

    // ---------------- LSTM epilogue ----------------
    const int par = lane & 1;
    const int rA = bm + wm * 16 + (lane >> 2);
    const int r  = rA + par * 8;
#pragma unroll
    for (int jt = 0; jt < 4; jt++) {
        const int cix = bn + wn * 32 + jt * 8 + (lane & 3) * 2;
        float z0 = acc[jt][0] + p.bias[cix];
        float z1 = acc[jt][1] + p.bias[cix + 1];
        float z2 = acc[jt][2] + p.bias[cix];
        float z3 = acc[jt][3] + p.bias[cix + 1];
        if (p.pre) {
            z0 += p.pre[(size_t)rA * p.preStride + cix];
            z1 += p.pre[(size_t)rA * p.preStride + cix + 1];
            z2 += p.pre[(size_t)(rA + 8) * p.preStride + cix];
            z3 += p.pre[(size_t)(rA + 8) * p.preStride + cix + 1];
        }
        float s0 = par ? z0 : z2;
        float s1 = par ? z1 : z3;
        float q0 = __shfl_xor_sync(0xffffffffu, s0, 1);
        float q1 = __shfl_xor_sync(0xffffffffu, s1, 1);
        float zi = par ? q0 : z0;
        float zf = par ? q1 : z1;
        float zg = par ? z2 : q0;
        float zo = par ? z3 : q1;
        const int j = cix >> 2;
        const size_t si = (size_t)r * NH + j;
        float ig = sigf(zi), fg = sigf(zf), og = sigf(zo);
        float gg = tanhff(zg);
        float cn = fg * p.cState[si] + ig * gg;
        float h = og * tanhff(cn);
        p.cState[si] = cn;
        __half hh = __float2half(h);
        p.hOut[si] = hh;
        if (p.yOut) p.yOut[(size_t)r * p.yStride + j] = hh;
        if (p.yF32) p.yF32[(size_t)r * p.yStride + j] = h;
    }
}

// ---------------- plain GEMM for the x@eW0 precompute ----------------
__global__ __launch_bounds__(256, 4)
void k_gemmN(const __half* __restrict__ A, int lda,
             const __half* __restrict__ B, int ldw,
             int nc, float* __restrict__ outZ) {
    extern __shared__ __align__(128) char smem[];
    const uint32_t sb = smem_u32(smem);
    const int tid = threadIdx.x, lane = tid & 31, warp = tid >> 5;
    const int wm = warp >> 2;
    const int wn = warp & 3;
    const int bm = blockIdx.x * 32;
    const int bn = blockIdx.y * 128;

    float acc[4][4];
#pragma unroll
    for (int b = 0; b < 4; b++)
#pragma unroll
        for (int c = 0; c < 4; c++) acc[b][c] = 0.0f;

    const uint32_t a_lc = (uint32_t)(lane & 16);
    const uint32_t b_lc = (uint32_t)((lane & 8) << 1);
    const int b_r8 = (lane & 16) >> 1;

    auto issue = [&](int c) {
        const int kb = c * 64;
        const uint32_t dbase = sb + (uint32_t)(c & 1) * BUF_STRIDE;
        {
            int row = tid >> 3, seg = tid & 7;
            uint32_t off = (uint32_t)(row * 128) + (uint32_t)((seg * 16) ^ ((row & 7) * 16));
            cpa16(dbase + off, A + (size_t)(bm + row) * lda + kb + seg * 8);
        }
        {
            const uint32_t db = dbase + 4096u;
#pragma unroll
            for (int it = 0; it < 4; it++) {
                int u = it * 256 + tid;
                int row = u >> 3, seg = u & 7;
                uint32_t off = (uint32_t)(row * 128) + (uint32_t)((seg * 16) ^ ((row & 7) * 16));
                cpa16(db + off, B + (size_t)(bn + row) * ldw + kb + seg * 8);
            }
        }
        CP_COMMIT();
    };

    issue(0);
    for (int c = 0; c < nc; ++c) {
        asm volatile("cp.async.wait_group 0;" ::: "memory");
        __syncthreads();
        if (c + 1 < nc) issue(c + 1);
        const uint32_t dbase = sb + (uint32_t)(c & 1) * BUF_STRIDE;
#pragma unroll
        for (int k16 = 0; k16 < 4; ++k16) {
            const uint32_t kcol = (uint32_t)(k16 * 32);
            uint32_t af[4];
            {
                int r = wm * 16 + (lane & 15);
                uint32_t addr = dbase + (uint32_t)(r * 128)
                              + ((kcol + a_lc) ^ (uint32_t)((r & 7) * 16));
                ldsm4(af, addr);
            }
            uint32_t bfr[4][2];
#pragma unroll
            for (int jq = 0; jq < 2; ++jq) {
                int r = wn * 32 + jq * 16 + (lane & 7) + b_r8;
                uint32_t addr = dbase + 4096u + (uint32_t)(r * 128)
                              + ((kcol + b_lc) ^ (uint32_t)((r & 7) * 16));
                uint32_t t4[4];
                ldsm4(t4, addr);
                bfr[jq * 2][0] = t4[0];     bfr[jq * 2][1] = t4[1];
                bfr[jq * 2 + 1][0] = t4[2]; bfr[jq * 2 + 1][1] = t4[3];
            }
#pragma unroll
            for (int jt = 0; jt < 4; ++jt)
                mma16816h(acc[jt], af, bfr[jt][0], bfr[jt][1]);
        }
    }

    int r = bm + wm * 16 + (lane >> 2);
#pragma unroll
    for (int jt = 0; jt < 4; jt++) {
        int cix = bn + wn * 32 + jt * 8 + (lane & 3) * 2;
        float* o = outZ + (size_t)r * NG + cix;
        o[0] = acc[jt][0]; o[1] = acc[jt][1];
        o += (size_t)8 * NG;
        o[0] = acc[jt][2]; o[1] = acc[jt][3];
    }
}

// ---------------- final dense ----------------
__global__ void k_dense(const float* __restrict__ w, const float* __restrict__ b,
                        float* __restrict__ out) {
    int r = blockIdx.x * 8 + (threadIdx.x >> 5);
    int lane = threadIdx.x & 31;
    const float* row = g_D1 + (size_t)r * NH;
    float s = 0.0f;
#pragma unroll
    for (int k = lane; k < NH; k += 32) s += row[k] * w[k];
#pragma unroll
    for (int o = 16; o; o >>= 1) s += __shfl_xor_sync(0xffffffffu, s, o);
    if (lane == 0) out[r] = s + b[0];
}

// ---------------- host ----------------
extern "C" void kernel_launch(void* const* d_in, const int* in_sizes, int n_in,
                              void* d_out, int out_size) {
    (void)in_sizes; (void)n_in; (void)out_size;
    const float* x      = (const float*)d_in[0];
    const float* eW0    = (const float*)d_in[2];
    const float* eU0    = (const float*)d_in[3];
    const float* eb0    = (const float*)d_in[4];
    const float* eW1    = (const float*)d_in[5];
    const float* eU1    = (const float*)d_in[6];
    const float* eb1    = (const float*)d_in[7];
    const float* dU0    = (const float*)d_in[9];
    const float* db0    = (const float*)d_in[10];
    const float* dW1    = (const float*)d_in[11];
    const float* dU1    = (const float*)d_in[12];
    const float* db1    = (const float*)d_in[13];
    const float* denseW = (const float*)d_in[14];
    const float* denseb = (const float*)d_in[15];

    cudaFuncSetAttribute(k_step,  cudaFuncAttributeMaxDynamicSharedMemorySize, SMEM_DYN);
    cudaFuncSetAttribute(k_gemmN, cudaFuncAttributeMaxDynamicSharedMemorySize, SMEM_DYN);

    void *pZ, *pX, *pY, *pD1, *pA, *pB, *pCA, *pCB, *pW, *pBs;
    cudaGetSymbolAddress(&pZ, g_Z);
    cudaGetSymbolAddress(&pX, g_X);
    cudaGetSymbolAddress(&pY, g_Y);
    cudaGetSymbolAddress(&pD1, g_D1);
    cudaGetSymbolAddress(&pA, g_hA);
    cudaGetSymbolAddress(&pB, g_hB);
    cudaGetSymbolAddress(&pCA, g_cA);  cudaGetSymbolAddress(&pCB, g_cB);
    cudaGetSymbolAddress(&pW, g_WT);
    cudaGetSymbolAddress(&pBs, g_bias);

    float* Z = (float*)pZ;
    __half* X = (__half*)pX;
    __half* Y = (__half*)pY;
    float* D1 = (float*)pD1;
    __half* hA[2] = {(__half*)pA, (__half*)pA + NB * NH};
    __half* hB[2] = {(__half*)pB, (__half*)pB + NB * NH};
    float* cA = (float*)pCA; float* cB = (float*)pCB;
    __half* W = (__half*)pW;
    float* Bias = (float*)pBs;

    // --- prep: 2 launches ---
    {
        long long wtot = 2048LL * 3200;
        k_prep_weights<<<(int)((wtot + 255) / 256), 256>>>(eW0, eU0, eW1, eU1, dU0, dW1, dU1);
        long long mtot = 4LL * NG + (long long)NB * NT * 128 + (long long)NB * NH;
        k_prep_misc<<<(int)((mtot + 255) / 256), 256>>>(x, eb0, eb1, db0, db1);
    }

    const dim3 blk(256);

    // --- x@eW0 precompute (K=128) ---
    k_gemmN<<<dim3(NB * NT / 32, 16), blk, SMEM_DYN>>>(X, 128, W + O_eW0, 128, 2, Z);

    // --- step param builders ---
    auto encL0 = [&](int t) {
        StepP p{};
        p.A = hA[t & 1]; p.lda = NH; p.A2 = nullptr; p.lda2 = 0;
        p.B = W + O_eU0; p.ldw = 512; p.nc = 8;
        p.pre = Z + (size_t)t * NG; p.preStride = (long long)NT * NG;
        p.bias = Bias + 0 * NG; p.cState = cA; p.hOut = hA[(t + 1) & 1];
        p.yOut = Y + (size_t)t * NH; p.yStride = (long long)NT * NH; p.yF32 = nullptr;
        return p;
    };
    auto encL1 = [&](int t) {
        StepP p{};
        p.A = hB[t & 1]; p.lda = NH;
        p.A2 = Y + (size_t)t * NH; p.lda2 = NT * NH;
        p.B = W + O_eUW1; p.ldw = 1024; p.nc = 16;
        p.pre = nullptr; p.preStride = 0;
        p.bias = Bias + 1 * NG; p.cState = cB; p.hOut = hB[(t + 1) & 1];
        p.yOut = nullptr; p.yStride = 0; p.yF32 = nullptr;
        return p;
    };
    auto decL0 = [&](int t) {
        StepP p{};
        p.A = hA[t & 1]; p.lda = NH; p.A2 = nullptr; p.lda2 = 0;
        p.B = W + O_dU0; p.ldw = 512; p.nc = 8;
        p.pre = nullptr; p.preStride = 0;
        p.bias = Bias + 2 * NG; p.cState = cA; p.hOut = hA[(t + 1) & 1];
        p.yOut = Y + (size_t)t * NH; p.yStride = (long long)NSEG * NH; p.yF32 = nullptr;
        return p;
    };
    auto decL1 = [&](int t) {
        StepP p{};
        p.A = hB[t & 1]; p.lda = NH;
        p.A2 = Y + (size_t)t * NH; p.lda2 = NSEG * NH;
        p.B = W + O_dUW1; p.ldw = 1024; p.nc = 16;
        p.pre = nullptr; p.preStride = 0;
        p.bias = Bias + 3 * NG; p.cState = cB; p.hOut = hB[(t + 1) & 1];
        p.yOut = nullptr; p.yStride = (long long)NSEG * NH; p.yF32 = D1 + (size_t)t * NH;
        return p;
    };

    const dim3 gSingle(NB / 32, 16, 1);
    const dim3 gDual(NB / 32, 16, 2);

    // --- encoder: dual-slot pipeline L0(s) || L1(s-1) ---
    {
        StepP p = encL0(0);
        k_step<<<gSingle, blk, SMEM_DYN>>>(p, p);
    }
    for (int s = 1; s < NT; s++) {
        k_step<<<gDual, blk, SMEM_DYN>>>(encL0(s), encL1(s - 1));
    }
    {
        StepP p = encL1(NT - 1);
        k_step<<<gSingle, blk, SMEM_DYN>>>(p, p);
    }
    // --- decoder: dual-slot pipeline dL0(s) || dL1(s-1) ---
    {
        StepP p = decL0(0);
        k_step<<<gSingle, blk, SMEM_DYN>>>(p, p);
    }
    for (int s = 1; s < NSEG; s++) {
        k_step<<<gDual, blk, SMEM_DYN>>>(decL0(s), decL1(s - 1));
    }
    {
        StepP p = decL1(NSEG - 1);
        k_step<<<gSingle, blk, SMEM_DYN>>>(p, p);
    }
    // --- final dense ---
    k_dense<<<NB * NSEG / 8, 256>>>(denseW, denseb, (float*)d_out);
}

// round 16
// speedup vs baseline: 1.4333x; 1.2482x over previous
#include <cuda_runtime.h>
#include <cuda_fp16.h>
#include <cstdint>
#include <cstddef>

#define NB 1024
#define NT 64
#define NF 121
#define NH 512
#define NSEG 32
#define NG 2048   // 4*H

// ---------------- scratch (device globals; no allocation) ----------------
__device__ __align__(16) float   g_Z   [(size_t)NB * NT * NG];    // x@eW0 pre (interleaved cols)
__device__ __align__(16) __half  g_X   [(size_t)NB * NT * 128];
__device__ __align__(16) __half  g_Y   [(size_t)NB * NT * NH];    // y0 / d0 staging (fp16)
__device__ __align__(16) float   g_D1  [(size_t)NB * NSEG * NH];
__device__ __align__(16) __half  g_hA  [2][NB * NH];
__device__ __align__(16) __half  g_hB  [2][NB * NH];
__device__ __align__(16) float   g_cA  [NB * NH];
__device__ __align__(16) float   g_cB  [NB * NH];
// weight arena: W^T fp16, rows = interleaved out-col (j*4+gate), K contiguous.
// Sections: eW0 (Kpad 128), eU0 (512), eUW1 = [eU1|eW1] (1024), dU0 (512), dUW1 = [dU1|dW1] (1024)
#define O_eW0  0
#define O_eU0  (2048*128)
#define O_eUW1 (O_eU0 + 2048*512)
#define O_dU0  (O_eUW1 + 2048*1024)
#define O_dUW1 (O_dU0 + 2048*512)
#define W_TOTAL (O_dUW1 + 2048*1024)
__device__ __align__(16) __half  g_WT  [W_TOTAL];
__device__ __align__(16) float   g_bias[4 * NG];

// ---------------- helpers ----------------
__device__ __forceinline__ float rcpa(float x) {
    float r; asm("rcp.approx.f32 %0, %1;" : "=f"(r) : "f"(x)); return r;
}
__device__ __forceinline__ float sigf(float x)  { return rcpa(1.0f + __expf(-x)); }
__device__ __forceinline__ float tanhff(float x){ return __fmaf_rn(2.0f, rcpa(1.0f + __expf(-2.0f * x)), -1.0f); }

__device__ __forceinline__ uint32_t smem_u32(const void* p) {
    uint32_t a;
    asm("{ .reg .u64 t; cvta.to.shared.u64 t, %1; cvt.u32.u64 %0, t; }" : "=r"(a) : "l"(p));
    return a;
}
__device__ __forceinline__ void mma16816h(float* d, const unsigned* a, unsigned b0, unsigned b1) {
    asm volatile(
        "mma.sync.aligned.m16n8k16.row.col.f32.f16.f16.f32 "
        "{%0,%1,%2,%3}, {%4,%5,%6,%7}, {%8,%9}, {%0,%1,%2,%3};"
        : "+f"(d[0]), "+f"(d[1]), "+f"(d[2]), "+f"(d[3])
        : "r"(a[0]), "r"(a[1]), "r"(a[2]), "r"(a[3]), "r"(b0), "r"(b1));
}
__device__ __forceinline__ void ldsm4(uint32_t* r, uint32_t addr) {
    asm volatile("ldmatrix.sync.aligned.m8n8.x4.shared.b16 {%0,%1,%2,%3}, [%4];"
                 : "=r"(r[0]), "=r"(r[1]), "=r"(r[2]), "=r"(r[3]) : "r"(addr));
}
__device__ __forceinline__ void cpa16(uint32_t dst, const void* src) {
    asm volatile("cp.async.cg.shared.global [%0], [%1], 16;" :: "r"(dst), "l"(src));
}
#define CP_COMMIT() asm volatile("cp.async.commit_group;" ::: "memory")

// smem: two 20KB stages: A 4K | B 16K  (40KB total -> 4 CTAs/SM)
#define BUF_STRIDE 20480u
#define SMEM_DYN   (2 * 20480)

// ---------------- merged prep kernels ----------------
__global__ void k_prep_weights(const float* __restrict__ eW0, const float* __restrict__ eU0,
                               const float* __restrict__ eW1, const float* __restrict__ eU1,
                               const float* __restrict__ dU0, const float* __restrict__ dW1,
                               const float* __restrict__ dU1) {
    long long idx = (long long)blockIdx.x * blockDim.x + threadIdx.x;
    const long long S128 = 2048LL * 128, S512 = 2048LL * 512, S1024 = 2048LL * 1024;
    const float *s0 = nullptr, *s1 = nullptr;
    int Kpad, K0;
    size_t off;
    if (idx < S128)              { s0 = eW0; K0 = NF;  Kpad = 128;  off = O_eW0; }
    else if ((idx -= S128) < S512)  { s0 = eU0; K0 = NH; Kpad = 512;  off = O_eU0; }
    else if ((idx -= S512) < S1024) { s0 = eU1; s1 = eW1; K0 = NH; Kpad = 1024; off = O_eUW1; }
    else if ((idx -= S1024) < S512) { s0 = dU0; K0 = NH; Kpad = 512;  off = O_dU0; }
    else if ((idx -= S512) < S1024) { s0 = dU1; s1 = dW1; K0 = NH; Kpad = 1024; off = O_dUW1; }
    else return;
    int n = (int)(idx / Kpad), k = (int)(idx % Kpad);
    float v;
    if (k < K0)           v = s0[(size_t)k * NG + n];
    else if (s1)          v = s1[(size_t)(k - 512) * NG + n];
    else                  v = 0.0f;
    int cil = (n & 511) * 4 + (n >> 9);
    g_WT[off + (size_t)cil * Kpad + k] = __float2half(v);
}

__global__ void k_prep_misc(const float* __restrict__ x,
                            const float* __restrict__ eb0, const float* __restrict__ eb1,
                            const float* __restrict__ db0, const float* __restrict__ db1) {
    long long idx = (long long)blockIdx.x * blockDim.x + threadIdx.x;
    if (idx < 4 * NG) {
        int which = (int)(idx >> 11), n = (int)(idx & 2047);
        const float* b = (which == 0) ? eb0 : (which == 1) ? eb1 : (which == 2) ? db0 : db1;
        g_bias[which * NG + (n & 511) * 4 + (n >> 9)] = b[n];
        return;
    }
    idx -= 4 * NG;
    if (idx < (long long)NB * NT * 128) {
        int r = (int)(idx >> 7), k = (int)(idx & 127);
        g_X[idx] = __float2half((k < NF) ? x[(size_t)r * NF + k] : 0.0f);
        return;
    }
    idx -= (long long)NB * NT * 128;
    if (idx < NB * NH) {
        __half z = __float2half(0.0f);
        g_hA[0][idx] = z; g_hB[0][idx] = z;
        g_cA[idx] = 0.0f; g_cB[idx] = 0.0f;
    }
}

// ---------------- step params ----------------
struct StepP {
    const __half* A;  int lda;      // K-half 0 (h state)
    const __half* A2; int lda2;     // K-half 1 (layer input) for NC=16
    const __half* B;  int ldw;      // weight rows, ldw = Kpad
    const float* pre; long long preStride;
    const float* bias;
    float* cState;
    __half* hOut;
    __half* yOut; long long yStride;
    float* yF32;
};

// ---------------- templated step body (fully unrolled chunk loop) ----------------
template <int NC, bool PRE>
__device__ __forceinline__ void step_body(const StepP& p) {
    extern __shared__ __align__(128) char smem[];
    const uint32_t sb = smem_u32(smem);
    const int tid = threadIdx.x, lane = tid & 31, warp = tid >> 5;
    const int wm = warp >> 2;
    const int wn = warp & 3;
    const int bm = blockIdx.x * 32;
    const int bn = blockIdx.y * 128;

    float acc[4][4];
#pragma unroll
    for (int b = 0; b < 4; b++)
#pragma unroll
        for (int c = 0; c < 4; c++) acc[b][c] = 0.0f;

    const uint32_t a_lc = (uint32_t)(lane & 16);
    const uint32_t b_lc = (uint32_t)((lane & 8) << 1);
    const int b_r8 = (lane & 16) >> 1;

    auto issue = [&](int c) {
        const uint32_t dbase = sb + (uint32_t)(c & 1) * BUF_STRIDE;
        {   // A: 32 rows x 128B; chunks >= 8 come from A2 (compile-time under unroll)
            const __half* Ab; int ldA; int kb;
            if (NC == 16 && c >= 8) { Ab = p.A2; ldA = p.lda2; kb = c * 64 - 512; }
            else                    { Ab = p.A;  ldA = p.lda;  kb = c * 64; }
            int row = tid >> 3, seg = tid & 7;
            uint32_t off = (uint32_t)(row * 128) + (uint32_t)((seg * 16) ^ ((row & 7) * 16));
            cpa16(dbase + off, Ab + (size_t)(bm + row) * ldA + kb + seg * 8);
        }
        {   // B: 128 rows x 128B
            const int kb = c * 64;
            const uint32_t db = dbase + 4096u;
#pragma unroll
            for (int it = 0; it < 4; it++) {
                int u = it * 256 + tid;
                int row = u >> 3, seg = u & 7;
                uint32_t off = (uint32_t)(row * 128) + (uint32_t)((seg * 16) ^ ((row & 7) * 16));
                cpa16(db + off, p.B + (size_t)(bn + row) * p.ldw + kb + seg * 8);
            }
        }
        CP_COMMIT();
    };

    issue(0);
#pragma unroll
    for (int c = 0; c < NC; ++c) {
        asm volatile("cp.async.wait_group 0;" ::: "memory");
        __syncthreads();
        if (c + 1 < NC) issue(c + 1);
        const uint32_t dbase = sb + (uint32_t)(c & 1) * BUF_STRIDE;
#pragma unroll
        for (int k16 = 0; k16 < 4; ++k16) {
            const uint32_t kcol = (uint32_t)(k16 * 32);
            uint32_t af[4];
            {
                int r = wm * 16 + (lane & 15);
                uint32_t addr = dbase + (uint32_t)(r * 128)
                              + ((kcol + a_lc) ^ (uint32_t)((r & 7) * 16));
                ldsm4(af, addr);
            }
            uint32_t bfr[4][2];
#pragma unroll
            for (int jq = 0; jq < 2; ++jq) {
                int r = wn * 32 + jq * 16 + (lane & 7) + b_r8;
                uint32_t addr = dbase + 4096u + (uint32_t)(r * 128)
                              + ((kcol + b_lc) ^ (uint32_t)((r & 7) * 16));
                uint32_t t4[4];
                ldsm4(t4, addr);
                bfr[jq * 2][0] = t4[0];     bfr[jq * 2][1] = t4[1];
                bfr[jq * 2 + 1][0] = t4[2]; bfr[jq * 2 + 1][1] = t4[3];
            }
#pragma unroll
            for (int jt = 0; jt < 4; ++jt)
                mma16816h(acc[jt], af, bfr[jt][0], bfr[jt][1]);
        }
    }

    // ---------------- LSTM epilogue ----------------
    const int par = lane & 1;
    const int rA = bm + wm * 16 + (lane >> 2);
    const int r  = rA + par * 8;
#pragma unroll
    for (int jt = 0; jt < 4; jt++) {
        const int cix = bn + wn * 32 + jt * 8 + (lane & 3) * 2;
        float z0 = acc[jt][0] + p.bias[cix];
        float z1 = acc[jt][1] + p.bias[cix + 1];
        float z2 = acc[jt][2] + p.bias[cix];
        float z3 = acc[jt][3] + p.bias[cix + 1];
        if (PRE) {
            z0 += p.pre[(size_t)rA * p.preStride + cix];
            z1 += p.pre[(size_t)rA * p.preStride + cix + 1];
            z2 += p.pre[(size_t)(rA + 8) * p.preStride + cix];
            z3 += p.pre[(size_t)(rA + 8) * p.preStride + cix + 1];
        }
        float s0 = par ? z0 : z2;
        float s1 = par ? z1 : z3;
        float q0 = __shfl_xor_sync(0xffffffffu, s0, 1);
        float q1 = __shfl_xor_sync(0xffffffffu, s1, 1);
        float zi = par ? q0 : z0;
        float zf = par ? q1 : z1;
        float zg = par ? z2 : q0;
        float zo = par ? z3 : q1;
        const int j = cix >> 2;
        const size_t si = (size_t)r * NH + j;
        float ig = sigf(zi), fg = sigf(zf), og = sigf(zo);
        float gg = tanhff(zg);
        float cn = fg * p.cState[si] + ig * gg;
        float h = og * tanhff(cn);
        p.cState[si] = cn;
        __half hh = __float2half(h);
        p.hOut[si] = hh;
        if (p.yOut) p.yOut[(size_t)r * p.yStride + j] = hh;
        if (p.yF32) p.yF32[(size_t)r * p.yStride + j] = h;
    }
}

// single-slot and dual-slot kernels (branch BEFORE touching params)
template <int NC, bool PRE>
__global__ __launch_bounds__(256, 4) void k_step1(StepP p) {
    step_body<NC, PRE>(p);
}
template <int NC0, bool PRE0, int NC1, bool PRE1>
__global__ __launch_bounds__(256, 4) void k_step2(StepP p0, StepP p1) {
    if (blockIdx.z == 0) step_body<NC0, PRE0>(p0);
    else                 step_body<NC1, PRE1>(p1);
}

// ---------------- plain GEMM for the x@eW0 precompute (K=128) ----------------
__global__ __launch_bounds__(256, 4)
void k_gemmN(const __half* __restrict__ A, int lda,
             const __half* __restrict__ B, int ldw,
             float* __restrict__ outZ) {
    extern __shared__ __align__(128) char smem[];
    const uint32_t sb = smem_u32(smem);
    const int tid = threadIdx.x, lane = tid & 31, warp = tid >> 5;
    const int wm = warp >> 2;
    const int wn = warp & 3;
    const int bm = blockIdx.x * 32;
    const int bn = blockIdx.y * 128;

    float acc[4][4];
#pragma unroll
    for (int b = 0; b < 4; b++)
#pragma unroll
        for (int c = 0; c < 4; c++) acc[b][c] = 0.0f;

    const uint32_t a_lc = (uint32_t)(lane & 16);
    const uint32_t b_lc = (uint32_t)((lane & 8) << 1);
    const int b_r8 = (lane & 16) >> 1;

    auto issue = [&](int c) {
        const int kb = c * 64;
        const uint32_t dbase = sb + (uint32_t)(c & 1) * BUF_STRIDE;
        {
            int row = tid >> 3, seg = tid & 7;
            uint32_t off = (uint32_t)(row * 128) + (uint32_t)((seg * 16) ^ ((row & 7) * 16));
            cpa16(dbase + off, A + (size_t)(bm + row) * lda + kb + seg * 8);
        }
        {
            const uint32_t db = dbase + 4096u;
#pragma unroll
            for (int it = 0; it < 4; it++) {
                int u = it * 256 + tid;
                int row = u >> 3, seg = u & 7;
                uint32_t off = (uint32_t)(row * 128) + (uint32_t)((seg * 16) ^ ((row & 7) * 16));
                cpa16(db + off, B + (size_t)(bn + row) * ldw + kb + seg * 8);
            }
        }
        CP_COMMIT();
    };

    issue(0);
#pragma unroll
    for (int c = 0; c < 2; ++c) {
        asm volatile("cp.async.wait_group 0;" ::: "memory");
        __syncthreads();
        if (c + 1 < 2) issue(c + 1);
        const uint32_t dbase = sb + (uint32_t)(c & 1) * BUF_STRIDE;
#pragma unroll
        for (int k16 = 0; k16 < 4; ++k16) {
            const uint32_t kcol = (uint32_t)(k16 * 32);
            uint32_t af[4];
            {
                int r = wm * 16 + (lane & 15);
                uint32_t addr = dbase + (uint32_t)(r * 128)
                              + ((kcol + a_lc) ^ (uint32_t)((r & 7) * 16));
                ldsm4(af, addr);
            }
            uint32_t bfr[4][2];
#pragma unroll
            for (int jq = 0; jq < 2; ++jq) {
                int r = wn * 32 + jq * 16 + (lane & 7) + b_r8;
                uint32_t addr = dbase + 4096u + (uint32_t)(r * 128)
                              + ((kcol + b_lc) ^ (uint32_t)((r & 7) * 16));
                uint32_t t4[4];
                ldsm4(t4, addr);
                bfr[jq * 2][0] = t4[0];     bfr[jq * 2][1] = t4[1];
                bfr[jq * 2 + 1][0] = t4[2]; bfr[jq * 2 + 1][1] = t4[3];
            }
#pragma unroll
            for (int jt = 0; jt < 4; ++jt)
                mma16816h(acc[jt], af, bfr[jt][0], bfr[jt][1]);
        }
    }

    int r = bm + wm * 16 + (lane >> 2);
#pragma unroll
    for (int jt = 0; jt < 4; jt++) {
        int cix = bn + wn * 32 + jt * 8 + (lane & 3) * 2;
        float* o = outZ + (size_t)r * NG + cix;
        o[0] = acc[jt][0]; o[1] = acc[jt][1];
        o += (size_t)8 * NG;
        o[0] = acc[jt][2]; o[1] = acc[jt][3];
    }
}

// ---------------- final dense ----------------
__global__ void k_dense(const float* __restrict__ w, const float* __restrict__ b,
                        float* __restrict__ out) {
    int r = blockIdx.x * 8 + (threadIdx.x >> 5);
    int lane = threadIdx.x & 31;
    const float* row = g_D1 + (size_t)r * NH;
    float s = 0.0f;
#pragma unroll
    for (int k = lane; k < NH; k += 32) s += row[k] * w[k];
#pragma unroll
    for (int o = 16; o; o >>= 1) s += __shfl_xor_sync(0xffffffffu, s, o);
    if (lane == 0) out[r] = s + b[0];
}

// ---------------- host ----------------
extern "C" void kernel_launch(void* const* d_in, const int* in_sizes, int n_in,
                              void* d_out, int out_size) {
    (void)in_sizes; (void)n_in; (void)out_size;
    const float* x      = (const float*)d_in[0];
    const float* eW0    = (const float*)d_in[2];
    const float* eU0    = (const float*)d_in[3];
    const float* eb0    = (const float*)d_in[4];
    const float* eW1    = (const float*)d_in[5];
    const float* eU1    = (const float*)d_in[6];
    const float* eb1    = (const float*)d_in[7];
    const float* dU0    = (const float*)d_in[9];
    const float* db0    = (const float*)d_in[10];
    const float* dW1    = (const float*)d_in[11];
    const float* dU1    = (const float*)d_in[12];
    const float* db1    = (const float*)d_in[13];
    const float* denseW = (const float*)d_in[14];
    const float* denseb = (const float*)d_in[15];

    cudaFuncSetAttribute(k_step1<8, true>,   cudaFuncAttributeMaxDynamicSharedMemorySize, SMEM_DYN);
    cudaFuncSetAttribute(k_step1<8, false>,  cudaFuncAttributeMaxDynamicSharedMemorySize, SMEM_DYN);
    cudaFuncSetAttribute(k_step1<16, false>, cudaFuncAttributeMaxDynamicSharedMemorySize, SMEM_DYN);
    cudaFuncSetAttribute((const void*)&k_step2<8, true, 16, false>,
                         cudaFuncAttributeMaxDynamicSharedMemorySize, SMEM_DYN);
    cudaFuncSetAttribute((const void*)&k_step2<8, false, 16, false>,
                         cudaFuncAttributeMaxDynamicSharedMemorySize, SMEM_DYN);
    cudaFuncSetAttribute(k_gemmN, cudaFuncAttributeMaxDynamicSharedMemorySize, SMEM_DYN);

    void *pZ, *pX, *pY, *pD1, *pA, *pB, *pCA, *pCB, *pW, *pBs;
    cudaGetSymbolAddress(&pZ, g_Z);
    cudaGetSymbolAddress(&pX, g_X);
    cudaGetSymbolAddress(&pY, g_Y);
    cudaGetSymbolAddress(&pD1, g_D1);
    cudaGetSymbolAddress(&pA, g_hA);
    cudaGetSymbolAddress(&pB, g_hB);
    cudaGetSymbolAddress(&pCA, g_cA);  cudaGetSymbolAddress(&pCB, g_cB);
    cudaGetSymbolAddress(&pW, g_WT);
    cudaGetSymbolAddress(&pBs, g_bias);

    float* Z = (float*)pZ;
    __half* X = (__half*)pX;
    __half* Y = (__half*)pY;
    float* D1 = (float*)pD1;
    __half* hA[2] = {(__half*)pA, (__half*)pA + NB * NH};
    __half* hB[2] = {(__half*)pB, (__half*)pB + NB * NH};
    float* cA = (float*)pCA; float* cB = (float*)pCB;
    __half* W = (__half*)pW;
    float* Bias = (float*)pBs;

    // --- prep: 2 launches ---
    {
        long long wtot = 2048LL * 3200;
        k_prep_weights<<<(int)((wtot + 255) / 256), 256>>>(eW0, eU0, eW1, eU1, dU0, dW1, dU1);
        long long mtot = 4LL * NG + (long long)NB * NT * 128 + (long long)NB * NH;
        k_prep_misc<<<(int)((mtot + 255) / 256), 256>>>(x, eb0, eb1, db0, db1);
    }

    const dim3 blk(256);

    // --- x@eW0 precompute (K=128) ---
    k_gemmN<<<dim3(NB * NT / 32, 16), blk, SMEM_DYN>>>(X, 128, W + O_eW0, 128, Z);

    // --- step param builders ---
    auto encL0 = [&](int t) {
        StepP p{};
        p.A = hA[t & 1]; p.lda = NH; p.A2 = nullptr; p.lda2 = 0;
        p.B = W + O_eU0; p.ldw = 512;
        p.pre = Z + (size_t)t * NG; p.preStride = (long long)NT * NG;
        p.bias = Bias + 0 * NG; p.cState = cA; p.hOut = hA[(t + 1) & 1];
        p.yOut = Y + (size_t)t * NH; p.yStride = (long long)NT * NH; p.yF32 = nullptr;
        return p;
    };
    auto encL1 = [&](int t) {
        StepP p{};
        p.A = hB[t & 1]; p.lda = NH;
        p.A2 = Y + (size_t)t * NH; p.lda2 = NT * NH;
        p.B = W + O_eUW1; p.ldw = 1024;
        p.pre = nullptr; p.preStride = 0;
        p.bias = Bias + 1 * NG; p.cState = cB; p.hOut = hB[(t + 1) & 1];
        p.yOut = nullptr; p.yStride = 0; p.yF32 = nullptr;
        return p;
    };
    auto decL0 = [&](int t) {
        StepP p{};
        p.A = hA[t & 1]; p.lda = NH; p.A2 = nullptr; p.lda2 = 0;
        p.B = W + O_dU0; p.ldw = 512;
        p.pre = nullptr; p.preStride = 0;
        p.bias = Bias + 2 * NG; p.cState = cA; p.hOut = hA[(t + 1) & 1];
        p.yOut = Y + (size_t)t * NH; p.yStride = (long long)NSEG * NH; p.yF32 = nullptr;
        return p;
    };
    auto decL1 = [&](int t) {
        StepP p{};
        p.A = hB[t & 1]; p.lda = NH;
        p.A2 = Y + (size_t)t * NH; p.lda2 = NSEG * NH;
        p.B = W + O_dUW1; p.ldw = 1024;
        p.pre = nullptr; p.preStride = 0;
        p.bias = Bias + 3 * NG; p.cState = cB; p.hOut = hB[(t + 1) & 1];
        p.yOut = nullptr; p.yStride = (long long)NSEG * NH; p.yF32 = D1 + (size_t)t * NH;
        return p;
    };

    const dim3 gSingle(NB / 32, 16, 1);
    const dim3 gDual(NB / 32, 16, 2);

    // --- encoder: dual-slot pipeline L0(s) || L1(s-1) ---
    k_step1<8, true><<<gSingle, blk, SMEM_DYN>>>(encL0(0));
    for (int s = 1; s < NT; s++) {
        k_step2<8, true, 16, false><<<gDual, blk, SMEM_DYN>>>(encL0(s), encL1(s - 1));
    }
    k_step1<16, false><<<gSingle, blk, SMEM_DYN>>>(encL1(NT - 1));
    // --- decoder: dual-slot pipeline dL0(s) || dL1(s-1) ---
    k_step1<8, false><<<gSingle, blk, SMEM_DYN>>>(decL0(0));
    for (int s = 1; s < NSEG; s++) {
        k_step2<8, false, 16, false><<<gDual, blk, SMEM_DYN>>>(decL0(s), decL1(s - 1));
    }
    k_step1<16, false><<<gSingle, blk, SMEM_DYN>>>(decL1(NSEG - 1));
    // --- final dense ---
    k_dense<<<NB * NSEG / 8, 256>>>(denseW, denseb, (float*)d_out);
}